// round 14
// baseline (speedup 1.0000x reference)
#include <cuda_runtime.h>
#include <cuda_fp16.h>
#include <cstdint>

// Problem constants: B=1, N=16, T=2048, E=64, H=4, D=16
#define NN   16
#define TT   2048
#define EE   64
#define HH   4
#define DD   16
#define NP   (NN*HH)          // 64 (n,h) pairs
// Q pre-scaled by log2(e)/8 so scores are in log2 domain -> ex2.approx (1 MUFU)
#define QSCALE2 0.180336880740290f

// ---------------------------------------------------------------------------
// Scratch (static device arrays; allocation-free per harness rules)
__device__ __align__(16) __half g_Qh[NP * TT * DD];  // q*log2e/8 (fp16)
__device__ __align__(16) __half g_Kh[NP * TT * DD];  // k (fp16)
__device__ __align__(16) float  g_V [NP * TT * DD];  // projected v (fp32)
__device__ __align__(16) __half g_Wh[NP * TT * DD];  // (v/Z) fp16
__device__ __align__(16) __half g_Oh[NN * TT * EE];  // attention out fp16

// ---------------------------------------------------------------------------
__device__ __forceinline__ uint32_t smem_u32(const void* p) {
    return (uint32_t)__cvta_generic_to_shared(p);
}
__device__ __forceinline__ void cp16(uint32_t dst, const void* src) {
    asm volatile("cp.async.cg.shared.global [%0], [%1], 16;" :: "r"(dst), "l"(src));
}
#define CP_COMMIT() asm volatile("cp.async.commit_group;")
#define CP_WAIT(n)  asm volatile("cp.async.wait_group %0;" :: "n"(n))

#define LDSM_X4(r0,r1,r2,r3,addr) \
    asm volatile("ldmatrix.sync.aligned.m8n8.x4.shared.b16 {%0,%1,%2,%3}, [%4];" \
        : "=r"(r0),"=r"(r1),"=r"(r2),"=r"(r3) : "r"(addr))
#define LDSM_X4T(r0,r1,r2,r3,addr) \
    asm volatile("ldmatrix.sync.aligned.m8n8.x4.trans.shared.b16 {%0,%1,%2,%3}, [%4];" \
        : "=r"(r0),"=r"(r1),"=r"(r2),"=r"(r3) : "r"(addr))
#define MMA16816(c0,c1,c2,c3,a0,a1,a2,a3,b0,b1) \
    asm volatile("mma.sync.aligned.m16n8k16.row.col.f32.f16.f16.f32 " \
        "{%0,%1,%2,%3},{%4,%5,%6,%7},{%8,%9},{%0,%1,%2,%3};" \
        : "+f"(c0),"+f"(c1),"+f"(c2),"+f"(c3) \
        : "r"(a0),"r"(a1),"r"(a2),"r"(a3),"r"(b0),"r"(b1))

__device__ __forceinline__ uint32_t h2u(__half2 h) {
    return reinterpret_cast<uint32_t&>(h);
}
__device__ __forceinline__ __half2 u2h(uint32_t u) {
    return reinterpret_cast<__half2&>(u);
}
// packed fp16x2 exp2 (1 MUFU op for 2 exps)
__device__ __forceinline__ uint32_t EX2H2(float a, float b) {
    uint32_t hin = h2u(__float22half2_rn(make_float2(a, b)));
    uint32_t r;
    asm("ex2.approx.f16x2 %0, %1;" : "=r"(r) : "r"(hin));
    return r;
}

// ---------------------------------------------------------------------------
// K1: head projections -> fp16 Q (log2e-scaled), fp16 K, fp32 V.
__global__ void k_proj(const float* __restrict__ value,
                       const float* __restrict__ key,
                       const float* __restrict__ query,
                       const float* __restrict__ Wq, const float* __restrict__ bq,
                       const float* __restrict__ Wk, const float* __restrict__ bk,
                       const float* __restrict__ Wv, const float* __restrict__ bv)
{
    __shared__ float sWq[256], sWk[256], sWv[256];
    __shared__ float sbq[16], sbk[16], sbv[16];
    int tid = threadIdx.x;
    if (tid < 256) { sWq[tid] = Wq[tid]; sWk[tid] = Wk[tid]; sWv[tid] = Wv[tid]; }
    if (tid < 16)  { sbq[tid] = bq[tid]; sbk[tid] = bk[tid]; sbv[tid] = bv[tid]; }
    __syncthreads();

    int id = blockIdx.x * blockDim.x + tid;
    int t  = id & (TT - 1);
    int p  = id >> 11;
    int n  = p >> 2;
    int h  = p & 3;
    int in_base  = (n * TT + t) * EE + h * DD;
    int out_base = (p * TT + t) * DD;

    float x[16];
    // ---- q (scaled by log2e/8) ----
    #pragma unroll
    for (int i = 0; i < 16; i++) x[i] = query[in_base + i];
    {
        float a[16];
        #pragma unroll
        for (int j = 0; j < 16; j++) {
            float acc = sbq[j];
            #pragma unroll
            for (int i = 0; i < 16; i++) acc = fmaf(x[i], sWq[i * 16 + j], acc);
            a[j] = acc * QSCALE2;
        }
        __half2* dh = reinterpret_cast<__half2*>(&g_Qh[out_base]);
        #pragma unroll
        for (int j = 0; j < 8; j++)
            dh[j] = __float22half2_rn(make_float2(a[2 * j], a[2 * j + 1]));
    }
    // ---- k ----
    #pragma unroll
    for (int i = 0; i < 16; i++) x[i] = key[in_base + i];
    {
        float a[16];
        #pragma unroll
        for (int j = 0; j < 16; j++) {
            float acc = sbk[j];
            #pragma unroll
            for (int i = 0; i < 16; i++) acc = fmaf(x[i], sWk[i * 16 + j], acc);
            a[j] = acc;
        }
        __half2* dh = reinterpret_cast<__half2*>(&g_Kh[out_base]);
        #pragma unroll
        for (int j = 0; j < 8; j++)
            dh[j] = __float22half2_rn(make_float2(a[2 * j], a[2 * j + 1]));
    }
    // ---- v (fp32) ----
    #pragma unroll
    for (int i = 0; i < 16; i++) x[i] = value[in_base + i];
    #pragma unroll
    for (int j = 0; j < 16; j++) {
        float acc = sbv[j];
        #pragma unroll
        for (int i = 0; i < 16; i++) acc = fmaf(x[i], sWv[i * 16 + j], acc);
        g_V[out_base + j] = acc;
    }
}

// ---------------------------------------------------------------------------
// K2 (pass A): Z[k] = sum_q exp2(qh.kh), then fold 1/Z into V in-place.
// Warp owns 64 k rows (4 A-frag sets) -> each Q b-frag LDSM feeds 8 MMAs.
// exp via ex2.approx.f16x2, bit-consistent with k_out's P path.
// grid = (TT/256, NP), block = 128 (4 warps x 64 k = 256 k rows / block).
__global__ void __launch_bounds__(128) k_zsum()
{
    __shared__ __align__(16) __half sK[256 * 16];
    __shared__ __align__(16) __half sQ[3][128 * 16];
    __shared__ float sZ[256];

    int tid = threadIdx.x, lane = tid & 31, warp = tid >> 5;
    int p = blockIdx.y, kbase = blockIdx.x * 256;

    // stage this block's 256 K rows: 512 uint4, 4 per thread
    {
        const uint4* src = reinterpret_cast<const uint4*>(g_Kh + (p * TT + kbase) * DD);
        uint4* dst = reinterpret_cast<uint4*>(sK);
        #pragma unroll
        for (int j = 0; j < 4; j++) dst[tid * 4 + j] = src[tid * 4 + j];
    }

    const __half* gq = g_Qh + p * TT * DD;
    // prologue: stage Q tiles 0, 1 (256 uint4 each, 2 per thread)
    #pragma unroll
    for (int qt0 = 0; qt0 < 2; qt0++) {
        uint32_t d = smem_u32(&sQ[qt0][0]);
        cp16(d + (tid * 2) * 16,     gq + qt0 * 128 * DD + (tid * 2) * 8);
        cp16(d + (tid * 2 + 1) * 16, gq + qt0 * 128 * DD + (tid * 2 + 1) * 8);
        CP_COMMIT();
    }

    __syncthreads();   // K tile visible

    // A frags: 4 sets of 16 K rows
    int g = lane >> 3;
    uint32_t akh[4][4];
    #pragma unroll
    for (int s = 0; s < 4; s++) {
        int row = warp * 64 + s * 16 + (g & 1) * 8 + (lane & 7);
        int col = (g >> 1) * 8;
        LDSM_X4(akh[s][0], akh[s][1], akh[s][2], akh[s][3], smem_u32(&sK[row * 16 + col]));
    }

    float z[4][2];
    #pragma unroll
    for (int s = 0; s < 4; s++) { z[s][0] = 0.f; z[s][1] = 0.f; }
    int browq = (g >> 1) * 8 + (lane & 7);
    int bcol  = (g & 1) * 8;

    for (int qt = 0; qt < 16; qt++) {
        if (qt < 15) { CP_WAIT(1); } else { CP_WAIT(0); }
        __syncthreads();
        int buf = qt % 3;
        uint32_t qb = smem_u32(&sQ[buf][browq * 16 + bcol]);
        #pragma unroll
        for (int sub = 0; sub < 8; sub++) {
            uint32_t bh0, bh1, bh2, bh3;
            LDSM_X4(bh0, bh1, bh2, bh3, qb + sub * 512);
            #pragma unroll
            for (int s = 0; s < 4; s++) {
                #pragma unroll
                for (int nh = 0; nh < 2; nh++) {
                    float c0 = 0.f, c1 = 0.f, c2 = 0.f, c3 = 0.f;
                    if (nh == 0) {
                        MMA16816(c0, c1, c2, c3, akh[s][0], akh[s][1], akh[s][2], akh[s][3], bh0, bh1);
                    } else {
                        MMA16816(c0, c1, c2, c3, akh[s][0], akh[s][1], akh[s][2], akh[s][3], bh2, bh3);
                    }
                    uint32_t e01 = EX2H2(c0, c1);
                    uint32_t e23 = EX2H2(c2, c3);
                    float2 f01 = __half22float2(u2h(e01));
                    float2 f23 = __half22float2(u2h(e23));
                    z[s][0] += f01.x + f01.y;
                    z[s][1] += f23.x + f23.y;
                }
            }
        }
        // stage tile qt+2
        if (qt + 2 < 16) {
            uint32_t d = smem_u32(&sQ[(qt + 2) % 3][0]);
            cp16(d + (tid * 2) * 16,     gq + (qt + 2) * 128 * DD + (tid * 2) * 8);
            cp16(d + (tid * 2 + 1) * 16, gq + (qt + 2) * 128 * DD + (tid * 2 + 1) * 8);
            CP_COMMIT();
        }
    }

    // quad reduce across the 4 threads sharing each row -> sZ
    #pragma unroll
    for (int s = 0; s < 4; s++)
        #pragma unroll
        for (int j = 0; j < 2; j++) {
            z[s][j] += __shfl_xor_sync(0xffffffffu, z[s][j], 1);
            z[s][j] += __shfl_xor_sync(0xffffffffu, z[s][j], 2);
        }
    if ((lane & 3) == 0) {
        int r = lane >> 2;
        #pragma unroll
        for (int s = 0; s < 4; s++) {
            sZ[warp * 64 + s * 16 + r]     = z[s][0];
            sZ[warp * 64 + s * 16 + r + 8] = z[s][1];
        }
    }
    __syncthreads();

    // fused fold: thread owns 2 k rows; W[k,:] = V[k,:]/Z[k] (fp16)
    #pragma unroll
    for (int half = 0; half < 2; half++) {
        int row = half * 128 + tid;
        int id = p * TT + kbase + row;
        float inv = 1.0f / sZ[row];
        const float4* v4 = reinterpret_cast<const float4*>(&g_V[id * DD]);
        __half2* dh = reinterpret_cast<__half2*>(&g_Wh[id * DD]);
        #pragma unroll
        for (int i = 0; i < 4; i++) {
            float4 x = v4[i];
            dh[2 * i]     = __float22half2_rn(make_float2(x.x * inv, x.y * inv));
            dh[2 * i + 1] = __float22half2_rn(make_float2(x.z * inv, x.w * inv));
        }
    }
}

// ---------------------------------------------------------------------------
// K4 (pass B): out[q,:] = sum_k exp2(qh.kh) * W[k,:]  (W pre-folded, fp16).
// Warp owns 64 q rows (4 A-frag sets) -> each K/W LDSM pair feeds 16 MMAs.
// P via ex2.approx.f16x2 (bit-consistent with k_zsum).
// grid = (TT/256, NP), block = 128 (4 warps x 64 q = 256 q rows / block).
__global__ void __launch_bounds__(128) k_out()
{
    __shared__ __align__(16) __half sQh[256 * 16];
    __shared__ __align__(16) __half sB[3][2][64 * 16];   // [buf][Kh,Wh]

    int tid = threadIdx.x, lane = tid & 31, warp = tid >> 5;
    int p = blockIdx.y, qbase = blockIdx.x * 256;
    int n = p >> 2, h = p & 3;

    // stage this block's 256 Q rows: 512 uint4, 4 per thread
    {
        const uint4* src = reinterpret_cast<const uint4*>(g_Qh + (p * TT + qbase) * DD);
        uint4* dst = reinterpret_cast<uint4*>(sQh);
        #pragma unroll
        for (int j = 0; j < 4; j++) dst[tid * 4 + j] = src[tid * 4 + j];
    }

    const __half* gk = g_Kh + p * TT * DD;
    const __half* gwh = g_Wh + p * TT * DD;
    uint32_t sb_base = smem_u32(&sB[0][0][0]);
    const uint32_t BUFB = 2 * 64 * 16 * 2;   // 4096 bytes per buffer

    // prologue: stage chunks 0, 1 (2 arrays x 128 slots; 2 cp16/thread)
    #pragma unroll
    for (int c0 = 0; c0 < 2; c0++) {
        uint32_t d = sb_base + c0 * BUFB;
        cp16(d + tid * 16,        gk  + c0 * 64 * DD + tid * 8);
        cp16(d + 2048 + tid * 16, gwh + c0 * 64 * DD + tid * 8);
        CP_COMMIT();
    }

    __syncthreads();   // Q tile visible

    // A frags: 4 sets of 16 Q rows
    int g = lane >> 3;
    uint32_t aqh[4][4];
    #pragma unroll
    for (int s = 0; s < 4; s++) {
        int row = warp * 64 + s * 16 + (g & 1) * 8 + (lane & 7);
        int col = (g >> 1) * 8;
        LDSM_X4(aqh[s][0], aqh[s][1], aqh[s][2], aqh[s][3], smem_u32(&sQh[row * 16 + col]));
    }

    float oc[4][2][4];   // [set][d-half][frag]
    #pragma unroll
    for (int s = 0; s < 4; s++)
        #pragma unroll
        for (int dh2 = 0; dh2 < 2; dh2++)
            #pragma unroll
            for (int j = 0; j < 4; j++) oc[s][dh2][j] = 0.f;

    uint32_t koff = ((g >> 1) * 8 + (lane & 7)) * 32 + (g & 1) * 16;
    uint32_t woff = 2048 + ((g & 1) * 8 + (lane & 7)) * 32 + (g >> 1) * 16;

    for (int kc = 0; kc < 32; kc++) {
        if (kc < 31) { CP_WAIT(1); } else { CP_WAIT(0); }
        __syncthreads();
        uint32_t bufb = sb_base + (kc % 3) * BUFB;
        uint32_t kaddr = bufb + koff;
        uint32_t waddr = bufb + woff;
        #pragma unroll
        for (int sub = 0; sub < 4; sub++) {
            uint32_t kh0, kh1, kh2, kh3;
            LDSM_X4(kh0, kh1, kh2, kh3, kaddr + sub * 512);
            uint32_t wh0, wh1, wh2, wh3;
            LDSM_X4T(wh0, wh1, wh2, wh3, waddr + sub * 512);

            #pragma unroll
            for (int s = 0; s < 4; s++) {
                uint32_t pah[4];
                {
                    float c0 = 0.f, c1 = 0.f, c2 = 0.f, c3 = 0.f;
                    MMA16816(c0, c1, c2, c3, aqh[s][0], aqh[s][1], aqh[s][2], aqh[s][3], kh0, kh1);
                    pah[0] = EX2H2(c0, c1);
                    pah[1] = EX2H2(c2, c3);
                }
                {
                    float c0 = 0.f, c1 = 0.f, c2 = 0.f, c3 = 0.f;
                    MMA16816(c0, c1, c2, c3, aqh[s][0], aqh[s][1], aqh[s][2], aqh[s][3], kh2, kh3);
                    pah[2] = EX2H2(c0, c1);
                    pah[3] = EX2H2(c2, c3);
                }

                MMA16816(oc[s][0][0], oc[s][0][1], oc[s][0][2], oc[s][0][3],
                         pah[0], pah[1], pah[2], pah[3], wh0, wh1);
                MMA16816(oc[s][1][0], oc[s][1][1], oc[s][1][2], oc[s][1][3],
                         pah[0], pah[1], pah[2], pah[3], wh2, wh3);
            }
        }
        // stage chunk kc+2
        if (kc + 2 < 32) {
            uint32_t d = sb_base + ((kc + 2) % 3) * BUFB;
            cp16(d + tid * 16,        gk  + (kc + 2) * 64 * DD + tid * 8);
            cp16(d + 2048 + tid * 16, gwh + (kc + 2) * 64 * DD + tid * 8);
            CP_COMMIT();
        }
    }

    // epilogue: write fp16 fragments to g_Oh (all 4 sets)
    {
        int r = lane >> 2, c2 = lane & 3;
        #pragma unroll
        for (int s = 0; s < 4; s++) {
            int q0 = qbase + warp * 64 + s * 16 + r;
            int b0i = (n * TT + q0) * EE + h * DD;
            int b8i = (n * TT + q0 + 8) * EE + h * DD;
            *reinterpret_cast<__half2*>(&g_Oh[b0i + 2 * c2]) =
                __float22half2_rn(make_float2(oc[s][0][0], oc[s][0][1]));
            *reinterpret_cast<__half2*>(&g_Oh[b8i + 2 * c2]) =
                __float22half2_rn(make_float2(oc[s][0][2], oc[s][0][3]));
            *reinterpret_cast<__half2*>(&g_Oh[b0i + 8 + 2 * c2]) =
                __float22half2_rn(make_float2(oc[s][1][0], oc[s][1][1]));
            *reinterpret_cast<__half2*>(&g_Oh[b8i + 8 + 2 * c2]) =
                __float22half2_rn(make_float2(oc[s][1][2], oc[s][1][3]));
        }
    }
}

// ---------------------------------------------------------------------------
// K5: final FC via HMMA: y = O @ Wfc + bfc.  X fp16, Wfc split hi/lo on the
// fly during smem staging (k_wsplit folded in — one fewer launch).
// grid = 256 blocks x 128 rows; block = 256 (8 warps, warp owns 16 rows).
__global__ void __launch_bounds__(256) k_fc_mma(const float* __restrict__ Wfc,
                                               const float* __restrict__ bfc,
                                               float* __restrict__ out)
{
    __shared__ __align__(16) __half sXh[128 * 64];
    __shared__ __align__(16) __half sWh[64 * 64],  sWl[64 * 64];
    __shared__ float sb[64];

    int tid = threadIdx.x, lane = tid & 31, warp = tid >> 5;
    int rowbase = blockIdx.x * 128;

    {
        const uint4* srch = reinterpret_cast<const uint4*>(g_Oh + rowbase * EE);
        uint4* dh = reinterpret_cast<uint4*>(sXh);
        #pragma unroll
        for (int j = 0; j < 4; j++)
            dh[tid + j * 256] = srch[tid + j * 256];
    }
    // stage + split Wfc: 4096 floats, 16 per thread
    #pragma unroll
    for (int j = 0; j < 16; j++) {
        int i = tid + j * 256;
        float w = Wfc[i];
        __half hi = __float2half_rn(w);
        sWh[i] = hi;
        sWl[i] = __float2half_rn(w - __half2float(hi));
    }
    if (tid < 64) sb[tid] = bfc[tid];
    __syncthreads();

    int g = lane >> 3;
    uint32_t axh[4][4];
    #pragma unroll
    for (int kt = 0; kt < 4; kt++) {
        int row = warp * 16 + (g & 1) * 8 + (lane & 7);
        int col = kt * 16 + (g >> 1) * 8;
        LDSM_X4(axh[kt][0], axh[kt][1], axh[kt][2], axh[kt][3], smem_u32(&sXh[row * 64 + col]));
    }

    float c[8][4];
    #pragma unroll
    for (int i = 0; i < 8; i++)
        #pragma unroll
        for (int j = 0; j < 4; j++) c[i][j] = 0.f;

    #pragma unroll
    for (int nt2 = 0; nt2 < 4; nt2++) {
        #pragma unroll
        for (int kt = 0; kt < 4; kt++) {
            int brow = kt * 16 + (g & 1) * 8 + (lane & 7);
            int bcol = nt2 * 16 + (g >> 1) * 8;
            uint32_t bh0, bh1, bh2, bh3, bl0, bl1, bl2, bl3;
            LDSM_X4T(bh0, bh1, bh2, bh3, smem_u32(&sWh[brow * 64 + bcol]));
            LDSM_X4T(bl0, bl1, bl2, bl3, smem_u32(&sWl[brow * 64 + bcol]));
            MMA16816(c[nt2*2][0], c[nt2*2][1], c[nt2*2][2], c[nt2*2][3],
                     axh[kt][0], axh[kt][1], axh[kt][2], axh[kt][3], bh0, bh1);
            MMA16816(c[nt2*2][0], c[nt2*2][1], c[nt2*2][2], c[nt2*2][3],
                     axh[kt][0], axh[kt][1], axh[kt][2], axh[kt][3], bl0, bl1);
            MMA16816(c[nt2*2+1][0], c[nt2*2+1][1], c[nt2*2+1][2], c[nt2*2+1][3],
                     axh[kt][0], axh[kt][1], axh[kt][2], axh[kt][3], bh2, bh3);
            MMA16816(c[nt2*2+1][0], c[nt2*2+1][1], c[nt2*2+1][2], c[nt2*2+1][3],
                     axh[kt][0], axh[kt][1], axh[kt][2], axh[kt][3], bl2, bl3);
        }
    }

    int r = lane >> 2, j = lane & 3;
    int row0 = rowbase + warp * 16 + r;
    #pragma unroll
    for (int nt = 0; nt < 8; nt++) {
        int ncol = nt * 8 + 2 * j;
        float b0 = sb[ncol], b1 = sb[ncol + 1];
        *reinterpret_cast<float2*>(&out[row0 * 64 + ncol]) =
            make_float2(c[nt][0] + b0, c[nt][1] + b1);
        *reinterpret_cast<float2*>(&out[(row0 + 8) * 64 + ncol]) =
            make_float2(c[nt][2] + b0, c[nt][3] + b1);
    }
}

// ---------------------------------------------------------------------------
// Input order: 0:value 1:key 2:query 3:Wq 4:bq 5:Wk 6:bk 7:Wv 8:bv 9:Wfc 10:bfc
extern "C" void kernel_launch(void* const* d_in, const int* in_sizes, int n_in,
                              void* d_out, int out_size)
{
    const float* value = (const float*)d_in[0];
    const float* key_  = (const float*)d_in[1];
    const float* query = (const float*)d_in[2];
    const float* Wq    = (const float*)d_in[3];
    const float* bq    = (const float*)d_in[4];
    const float* Wk    = (const float*)d_in[5];
    const float* bk    = (const float*)d_in[6];
    const float* Wv    = (const float*)d_in[7];
    const float* bv    = (const float*)d_in[8];
    const float* Wfc   = (const float*)d_in[9];
    const float* bfc   = (const float*)d_in[10];
    float* out = (float*)d_out;

    k_proj<<<(NP * TT) / 256, 256>>>(value, key_, query, Wq, bq, Wk, bk, Wv, bv);
    k_zsum<<<dim3(TT / 256, NP), 128>>>();
    k_out<<<dim3(TT / 256, NP), 128>>>();
    k_fc_mma<<<(NN * TT) / 128, 256>>>(Wfc, bfc, out);
}

// round 15
// speedup vs baseline: 1.0462x; 1.0462x over previous
#include <cuda_runtime.h>
#include <cuda_fp16.h>
#include <cstdint>

// Problem constants: B=1, N=16, T=2048, E=64, H=4, D=16
#define NN   16
#define TT   2048
#define EE   64
#define HH   4
#define DD   16
#define NP   (NN*HH)          // 64 (n,h) pairs
// Q pre-scaled by log2(e)/8 so scores are in log2 domain -> ex2.approx (1 MUFU)
#define QSCALE2 0.180336880740290f

// ---------------------------------------------------------------------------
// Scratch (static device arrays; allocation-free per harness rules)
__device__ __align__(16) __half g_Qh[NP * TT * DD];  // q*log2e/8 (fp16)
__device__ __align__(16) __half g_Kh[NP * TT * DD];  // k (fp16)
__device__ __align__(16) float  g_V [NP * TT * DD];  // projected v (fp32)
__device__ __align__(16) __half g_Wh[NP * TT * DD];  // (v/Z) fp16
__device__ __align__(16) __half g_Oh[NN * TT * EE];  // attention out fp16

// ---------------------------------------------------------------------------
__device__ __forceinline__ uint32_t smem_u32(const void* p) {
    return (uint32_t)__cvta_generic_to_shared(p);
}
__device__ __forceinline__ void cp16(uint32_t dst, const void* src) {
    asm volatile("cp.async.cg.shared.global [%0], [%1], 16;" :: "r"(dst), "l"(src));
}
#define CP_COMMIT() asm volatile("cp.async.commit_group;")
#define CP_WAIT(n)  asm volatile("cp.async.wait_group %0;" :: "n"(n))

#define LDSM_X4(r0,r1,r2,r3,addr) \
    asm volatile("ldmatrix.sync.aligned.m8n8.x4.shared.b16 {%0,%1,%2,%3}, [%4];" \
        : "=r"(r0),"=r"(r1),"=r"(r2),"=r"(r3) : "r"(addr))
#define LDSM_X4T(r0,r1,r2,r3,addr) \
    asm volatile("ldmatrix.sync.aligned.m8n8.x4.trans.shared.b16 {%0,%1,%2,%3}, [%4];" \
        : "=r"(r0),"=r"(r1),"=r"(r2),"=r"(r3) : "r"(addr))
#define MMA16816(c0,c1,c2,c3,a0,a1,a2,a3,b0,b1) \
    asm volatile("mma.sync.aligned.m16n8k16.row.col.f32.f16.f16.f32 " \
        "{%0,%1,%2,%3},{%4,%5,%6,%7},{%8,%9},{%0,%1,%2,%3};" \
        : "+f"(c0),"+f"(c1),"+f"(c2),"+f"(c3) \
        : "r"(a0),"r"(a1),"r"(a2),"r"(a3),"r"(b0),"r"(b1))

__device__ __forceinline__ uint32_t h2u(__half2 h) {
    return reinterpret_cast<uint32_t&>(h);
}
__device__ __forceinline__ __half2 u2h(uint32_t u) {
    return reinterpret_cast<__half2&>(u);
}
// packed fp16x2 exp2 (1 MUFU op for 2 exps)
__device__ __forceinline__ uint32_t EX2H2(float a, float b) {
    uint32_t hin = h2u(__float22half2_rn(make_float2(a, b)));
    uint32_t r;
    asm("ex2.approx.f16x2 %0, %1;" : "=r"(r) : "r"(hin));
    return r;
}

// ---------------------------------------------------------------------------
// K1: head projections -> fp16 Q (log2e-scaled), fp16 K, fp32 V.
__global__ void k_proj(const float* __restrict__ value,
                       const float* __restrict__ key,
                       const float* __restrict__ query,
                       const float* __restrict__ Wq, const float* __restrict__ bq,
                       const float* __restrict__ Wk, const float* __restrict__ bk,
                       const float* __restrict__ Wv, const float* __restrict__ bv)
{
    __shared__ float sWq[256], sWk[256], sWv[256];
    __shared__ float sbq[16], sbk[16], sbv[16];
    int tid = threadIdx.x;
    if (tid < 256) { sWq[tid] = Wq[tid]; sWk[tid] = Wk[tid]; sWv[tid] = Wv[tid]; }
    if (tid < 16)  { sbq[tid] = bq[tid]; sbk[tid] = bk[tid]; sbv[tid] = bv[tid]; }
    __syncthreads();

    int id = blockIdx.x * blockDim.x + tid;
    int t  = id & (TT - 1);
    int p  = id >> 11;
    int n  = p >> 2;
    int h  = p & 3;
    int in_base  = (n * TT + t) * EE + h * DD;
    int out_base = (p * TT + t) * DD;

    float x[16];
    // ---- q (scaled by log2e/8) ----
    #pragma unroll
    for (int i = 0; i < 16; i++) x[i] = query[in_base + i];
    {
        float a[16];
        #pragma unroll
        for (int j = 0; j < 16; j++) {
            float acc = sbq[j];
            #pragma unroll
            for (int i = 0; i < 16; i++) acc = fmaf(x[i], sWq[i * 16 + j], acc);
            a[j] = acc * QSCALE2;
        }
        __half2* dh = reinterpret_cast<__half2*>(&g_Qh[out_base]);
        #pragma unroll
        for (int j = 0; j < 8; j++)
            dh[j] = __float22half2_rn(make_float2(a[2 * j], a[2 * j + 1]));
    }
    // ---- k ----
    #pragma unroll
    for (int i = 0; i < 16; i++) x[i] = key[in_base + i];
    {
        float a[16];
        #pragma unroll
        for (int j = 0; j < 16; j++) {
            float acc = sbk[j];
            #pragma unroll
            for (int i = 0; i < 16; i++) acc = fmaf(x[i], sWk[i * 16 + j], acc);
            a[j] = acc;
        }
        __half2* dh = reinterpret_cast<__half2*>(&g_Kh[out_base]);
        #pragma unroll
        for (int j = 0; j < 8; j++)
            dh[j] = __float22half2_rn(make_float2(a[2 * j], a[2 * j + 1]));
    }
    // ---- v (fp32) ----
    #pragma unroll
    for (int i = 0; i < 16; i++) x[i] = value[in_base + i];
    #pragma unroll
    for (int j = 0; j < 16; j++) {
        float acc = sbv[j];
        #pragma unroll
        for (int i = 0; i < 16; i++) acc = fmaf(x[i], sWv[i * 16 + j], acc);
        g_V[out_base + j] = acc;
    }
}

// ---------------------------------------------------------------------------
// K2 (pass A): Z[k] = sum_q exp2(qh.kh), then fold 1/Z into V in-place.
// S hi-only (1 MMA per n8 tile); exp via ex2.approx.f16x2 — the SAME fp16
// rounding + ex2 path k_out uses, so the softmax is exactly consistent.
// Warp owns 32 k rows (round-13 tile: 64-row tiles regressed via occupancy).
// grid = (TT/128, NP), block = 128.
__global__ void __launch_bounds__(128) k_zsum()
{
    __shared__ __align__(16) __half sK[128 * 16];
    __shared__ __align__(16) __half sQ[3][128 * 16];
    __shared__ float sZ[128];

    int tid = threadIdx.x, lane = tid & 31, warp = tid >> 5;
    int p = blockIdx.y, kbase = blockIdx.x * 128;

    // stage this block's 128 K rows: 256 uint4, 2 per thread
    {
        const uint4* src = reinterpret_cast<const uint4*>(g_Kh + (p * TT + kbase) * DD);
        uint4* dst = reinterpret_cast<uint4*>(sK);
        dst[tid * 2] = src[tid * 2];
        dst[tid * 2 + 1] = src[tid * 2 + 1];
    }

    const __half* gq = g_Qh + p * TT * DD;
    // prologue: stage Q tiles 0, 1 (256 uint4 each, 2 per thread)
    #pragma unroll
    for (int qt0 = 0; qt0 < 2; qt0++) {
        uint32_t d = smem_u32(&sQ[qt0][0]);
        cp16(d + (tid * 2) * 16,     gq + qt0 * 128 * DD + (tid * 2) * 8);
        cp16(d + (tid * 2 + 1) * 16, gq + qt0 * 128 * DD + (tid * 2 + 1) * 8);
        CP_COMMIT();
    }

    __syncthreads();   // K tile visible

    // A frags: 2 sets of 16 K rows
    int g = lane >> 3;
    uint32_t akh[2][4];
    #pragma unroll
    for (int s = 0; s < 2; s++) {
        int row = warp * 32 + s * 16 + (g & 1) * 8 + (lane & 7);
        int col = (g >> 1) * 8;
        LDSM_X4(akh[s][0], akh[s][1], akh[s][2], akh[s][3], smem_u32(&sK[row * 16 + col]));
    }

    float z[2][2] = {{0.f, 0.f}, {0.f, 0.f}};
    int browq = (g >> 1) * 8 + (lane & 7);
    int bcol  = (g & 1) * 8;

    for (int qt = 0; qt < 16; qt++) {
        if (qt < 15) { CP_WAIT(1); } else { CP_WAIT(0); }
        __syncthreads();
        int buf = qt % 3;
        uint32_t qb = smem_u32(&sQ[buf][browq * 16 + bcol]);
        #pragma unroll
        for (int sub = 0; sub < 8; sub++) {
            uint32_t bh0, bh1, bh2, bh3;
            LDSM_X4(bh0, bh1, bh2, bh3, qb + sub * 512);
            #pragma unroll
            for (int s = 0; s < 2; s++) {
                #pragma unroll
                for (int nh = 0; nh < 2; nh++) {
                    float c0 = 0.f, c1 = 0.f, c2 = 0.f, c3 = 0.f;
                    if (nh == 0) {
                        MMA16816(c0, c1, c2, c3, akh[s][0], akh[s][1], akh[s][2], akh[s][3], bh0, bh1);
                    } else {
                        MMA16816(c0, c1, c2, c3, akh[s][0], akh[s][1], akh[s][2], akh[s][3], bh2, bh3);
                    }
                    uint32_t e01 = EX2H2(c0, c1);
                    uint32_t e23 = EX2H2(c2, c3);
                    float2 f01 = __half22float2(u2h(e01));
                    float2 f23 = __half22float2(u2h(e23));
                    z[s][0] += f01.x + f01.y;
                    z[s][1] += f23.x + f23.y;
                }
            }
        }
        // stage tile qt+2
        if (qt + 2 < 16) {
            uint32_t d = smem_u32(&sQ[(qt + 2) % 3][0]);
            cp16(d + (tid * 2) * 16,     gq + (qt + 2) * 128 * DD + (tid * 2) * 8);
            cp16(d + (tid * 2 + 1) * 16, gq + (qt + 2) * 128 * DD + (tid * 2 + 1) * 8);
            CP_COMMIT();
        }
    }

    // quad reduce across the 4 threads sharing each row -> sZ
    #pragma unroll
    for (int s = 0; s < 2; s++)
        #pragma unroll
        for (int j = 0; j < 2; j++) {
            z[s][j] += __shfl_xor_sync(0xffffffffu, z[s][j], 1);
            z[s][j] += __shfl_xor_sync(0xffffffffu, z[s][j], 2);
        }
    if ((lane & 3) == 0) {
        int r = lane >> 2;
        #pragma unroll
        for (int s = 0; s < 2; s++) {
            sZ[warp * 32 + s * 16 + r]     = z[s][0];
            sZ[warp * 32 + s * 16 + r + 8] = z[s][1];
        }
    }
    __syncthreads();

    // fused fold: thread owns one k row; W[k,:] = V[k,:]/Z[k] (fp16)
    {
        int id = p * TT + kbase + tid;
        float inv = 1.0f / sZ[tid];
        const float4* v4 = reinterpret_cast<const float4*>(&g_V[id * DD]);
        __half2* dh = reinterpret_cast<__half2*>(&g_Wh[id * DD]);
        #pragma unroll
        for (int i = 0; i < 4; i++) {
            float4 x = v4[i];
            dh[2 * i]     = __float22half2_rn(make_float2(x.x * inv, x.y * inv));
            dh[2 * i + 1] = __float22half2_rn(make_float2(x.z * inv, x.w * inv));
        }
    }
}

// ---------------------------------------------------------------------------
// K4 (pass B): out[q,:] = sum_k exp2(qh.kh) * W[k,:]  (W pre-folded, fp16).
// S hi-only; P via ex2.approx.f16x2 (bit-consistent with k_zsum); W fp16.
// Warp owns 32 q rows (round-13 tile).  64-k chunks, 3-deep cp.async.
// grid = (TT/128, NP), block = 128.
__global__ void __launch_bounds__(128) k_out()
{
    __shared__ __align__(16) __half sQh[128 * 16];
    __shared__ __align__(16) __half sB[3][2][64 * 16];   // [buf][Kh,Wh]

    int tid = threadIdx.x, lane = tid & 31, warp = tid >> 5;
    int p = blockIdx.y, qbase = blockIdx.x * 128;
    int n = p >> 2, h = p & 3;

    // stage this block's 128 Q rows: 256 uint4, 2 per thread
    {
        const uint4* src = reinterpret_cast<const uint4*>(g_Qh + (p * TT + qbase) * DD);
        uint4* dst = reinterpret_cast<uint4*>(sQh);
        dst[tid * 2] = src[tid * 2];
        dst[tid * 2 + 1] = src[tid * 2 + 1];
    }

    const __half* gk = g_Kh + p * TT * DD;
    const __half* gwh = g_Wh + p * TT * DD;
    uint32_t sb_base = smem_u32(&sB[0][0][0]);
    const uint32_t BUFB = 2 * 64 * 16 * 2;   // 4096 bytes per buffer

    // prologue: stage chunks 0, 1 (2 arrays x 128 slots; 2 cp16/thread)
    #pragma unroll
    for (int c0 = 0; c0 < 2; c0++) {
        uint32_t d = sb_base + c0 * BUFB;
        cp16(d + tid * 16,        gk  + c0 * 64 * DD + tid * 8);
        cp16(d + 2048 + tid * 16, gwh + c0 * 64 * DD + tid * 8);
        CP_COMMIT();
    }

    __syncthreads();   // Q tile visible

    // A frags: 2 sets of 16 Q rows
    int g = lane >> 3;
    uint32_t aqh[2][4];
    #pragma unroll
    for (int s = 0; s < 2; s++) {
        int row = warp * 32 + s * 16 + (g & 1) * 8 + (lane & 7);
        int col = (g >> 1) * 8;
        LDSM_X4(aqh[s][0], aqh[s][1], aqh[s][2], aqh[s][3], smem_u32(&sQh[row * 16 + col]));
    }

    float oc[2][2][4];   // [set][d-half][frag]
    #pragma unroll
    for (int s = 0; s < 2; s++)
        #pragma unroll
        for (int dh2 = 0; dh2 < 2; dh2++)
            #pragma unroll
            for (int j = 0; j < 4; j++) oc[s][dh2][j] = 0.f;

    uint32_t koff = ((g >> 1) * 8 + (lane & 7)) * 32 + (g & 1) * 16;
    uint32_t woff = 2048 + ((g & 1) * 8 + (lane & 7)) * 32 + (g >> 1) * 16;

    for (int kc = 0; kc < 32; kc++) {
        if (kc < 31) { CP_WAIT(1); } else { CP_WAIT(0); }
        __syncthreads();
        uint32_t bufb = sb_base + (kc % 3) * BUFB;
        uint32_t kaddr = bufb + koff;
        uint32_t waddr = bufb + woff;
        #pragma unroll
        for (int sub = 0; sub < 4; sub++) {
            uint32_t kh0, kh1, kh2, kh3;
            LDSM_X4(kh0, kh1, kh2, kh3, kaddr + sub * 512);
            uint32_t wh0, wh1, wh2, wh3;
            LDSM_X4T(wh0, wh1, wh2, wh3, waddr + sub * 512);

            #pragma unroll
            for (int s = 0; s < 2; s++) {
                uint32_t pah[4];
                {
                    float c0 = 0.f, c1 = 0.f, c2 = 0.f, c3 = 0.f;
                    MMA16816(c0, c1, c2, c3, aqh[s][0], aqh[s][1], aqh[s][2], aqh[s][3], kh0, kh1);
                    pah[0] = EX2H2(c0, c1);
                    pah[1] = EX2H2(c2, c3);
                }
                {
                    float c0 = 0.f, c1 = 0.f, c2 = 0.f, c3 = 0.f;
                    MMA16816(c0, c1, c2, c3, aqh[s][0], aqh[s][1], aqh[s][2], aqh[s][3], kh2, kh3);
                    pah[2] = EX2H2(c0, c1);
                    pah[3] = EX2H2(c2, c3);
                }

                MMA16816(oc[s][0][0], oc[s][0][1], oc[s][0][2], oc[s][0][3],
                         pah[0], pah[1], pah[2], pah[3], wh0, wh1);
                MMA16816(oc[s][1][0], oc[s][1][1], oc[s][1][2], oc[s][1][3],
                         pah[0], pah[1], pah[2], pah[3], wh2, wh3);
            }
        }
        // stage chunk kc+2
        if (kc + 2 < 32) {
            uint32_t d = sb_base + ((kc + 2) % 3) * BUFB;
            cp16(d + tid * 16,        gk  + (kc + 2) * 64 * DD + tid * 8);
            cp16(d + 2048 + tid * 16, gwh + (kc + 2) * 64 * DD + tid * 8);
            CP_COMMIT();
        }
    }

    // epilogue: write fp16 fragments to g_Oh (both sets)
    {
        int r = lane >> 2, c2 = lane & 3;
        #pragma unroll
        for (int s = 0; s < 2; s++) {
            int q0 = qbase + warp * 32 + s * 16 + r;
            int b0i = (n * TT + q0) * EE + h * DD;
            int b8i = (n * TT + q0 + 8) * EE + h * DD;
            *reinterpret_cast<__half2*>(&g_Oh[b0i + 2 * c2]) =
                __float22half2_rn(make_float2(oc[s][0][0], oc[s][0][1]));
            *reinterpret_cast<__half2*>(&g_Oh[b8i + 2 * c2]) =
                __float22half2_rn(make_float2(oc[s][0][2], oc[s][0][3]));
            *reinterpret_cast<__half2*>(&g_Oh[b0i + 8 + 2 * c2]) =
                __float22half2_rn(make_float2(oc[s][1][0], oc[s][1][1]));
            *reinterpret_cast<__half2*>(&g_Oh[b8i + 8 + 2 * c2]) =
                __float22half2_rn(make_float2(oc[s][1][2], oc[s][1][3]));
        }
    }
}

// ---------------------------------------------------------------------------
// K5: final FC via HMMA: y = O @ Wfc + bfc.  X fp16, Wfc split hi/lo on the
// fly during smem staging (wsplit fused — one fewer launch).
// grid = 256 blocks x 128 rows; block = 256 (8 warps, warp owns 16 rows).
__global__ void __launch_bounds__(256) k_fc_mma(const float* __restrict__ Wfc,
                                               const float* __restrict__ bfc,
                                               float* __restrict__ out)
{
    __shared__ __align__(16) __half sXh[128 * 64];
    __shared__ __align__(16) __half sWh[64 * 64],  sWl[64 * 64];
    __shared__ float sb[64];

    int tid = threadIdx.x, lane = tid & 31, warp = tid >> 5;
    int rowbase = blockIdx.x * 128;

    {
        const uint4* srch = reinterpret_cast<const uint4*>(g_Oh + rowbase * EE);
        uint4* dh = reinterpret_cast<uint4*>(sXh);
        #pragma unroll
        for (int j = 0; j < 4; j++)
            dh[tid + j * 256] = srch[tid + j * 256];
    }
    // stage + split Wfc: 4096 floats, 16 per thread
    #pragma unroll
    for (int j = 0; j < 16; j++) {
        int i = tid + j * 256;
        float w = Wfc[i];
        __half hi = __float2half_rn(w);
        sWh[i] = hi;
        sWl[i] = __float2half_rn(w - __half2float(hi));
    }
    if (tid < 64) sb[tid] = bfc[tid];
    __syncthreads();

    int g = lane >> 3;
    uint32_t axh[4][4];
    #pragma unroll
    for (int kt = 0; kt < 4; kt++) {
        int row = warp * 16 + (g & 1) * 8 + (lane & 7);
        int col = kt * 16 + (g >> 1) * 8;
        LDSM_X4(axh[kt][0], axh[kt][1], axh[kt][2], axh[kt][3], smem_u32(&sXh[row * 64 + col]));
    }

    float c[8][4];
    #pragma unroll
    for (int i = 0; i < 8; i++)
        #pragma unroll
        for (int j = 0; j < 4; j++) c[i][j] = 0.f;

    #pragma unroll
    for (int nt2 = 0; nt2 < 4; nt2++) {
        #pragma unroll
        for (int kt = 0; kt < 4; kt++) {
            int brow = kt * 16 + (g & 1) * 8 + (lane & 7);
            int bcol = nt2 * 16 + (g >> 1) * 8;
            uint32_t bh0, bh1, bh2, bh3, bl0, bl1, bl2, bl3;
            LDSM_X4T(bh0, bh1, bh2, bh3, smem_u32(&sWh[brow * 64 + bcol]));
            LDSM_X4T(bl0, bl1, bl2, bl3, smem_u32(&sWl[brow * 64 + bcol]));
            MMA16816(c[nt2*2][0], c[nt2*2][1], c[nt2*2][2], c[nt2*2][3],
                     axh[kt][0], axh[kt][1], axh[kt][2], axh[kt][3], bh0, bh1);
            MMA16816(c[nt2*2][0], c[nt2*2][1], c[nt2*2][2], c[nt2*2][3],
                     axh[kt][0], axh[kt][1], axh[kt][2], axh[kt][3], bl0, bl1);
            MMA16816(c[nt2*2+1][0], c[nt2*2+1][1], c[nt2*2+1][2], c[nt2*2+1][3],
                     axh[kt][0], axh[kt][1], axh[kt][2], axh[kt][3], bh2, bh3);
            MMA16816(c[nt2*2+1][0], c[nt2*2+1][1], c[nt2*2+1][2], c[nt2*2+1][3],
                     axh[kt][0], axh[kt][1], axh[kt][2], axh[kt][3], bl2, bl3);
        }
    }

    int r = lane >> 2, j = lane & 3;
    int row0 = rowbase + warp * 16 + r;
    #pragma unroll
    for (int nt = 0; nt < 8; nt++) {
        int ncol = nt * 8 + 2 * j;
        float b0 = sb[ncol], b1 = sb[ncol + 1];
        *reinterpret_cast<float2*>(&out[row0 * 64 + ncol]) =
            make_float2(c[nt][0] + b0, c[nt][1] + b1);
        *reinterpret_cast<float2*>(&out[(row0 + 8) * 64 + ncol]) =
            make_float2(c[nt][2] + b0, c[nt][3] + b1);
    }
}

// ---------------------------------------------------------------------------
// Input order: 0:value 1:key 2:query 3:Wq 4:bq 5:Wk 6:bk 7:Wv 8:bv 9:Wfc 10:bfc
extern "C" void kernel_launch(void* const* d_in, const int* in_sizes, int n_in,
                              void* d_out, int out_size)
{
    const float* value = (const float*)d_in[0];
    const float* key_  = (const float*)d_in[1];
    const float* query = (const float*)d_in[2];
    const float* Wq    = (const float*)d_in[3];
    const float* bq    = (const float*)d_in[4];
    const float* Wk    = (const float*)d_in[5];
    const float* bk    = (const float*)d_in[6];
    const float* Wv    = (const float*)d_in[7];
    const float* bv    = (const float*)d_in[8];
    const float* Wfc   = (const float*)d_in[9];
    const float* bfc   = (const float*)d_in[10];
    float* out = (float*)d_out;

    k_proj<<<(NP * TT) / 256, 256>>>(value, key_, query, Wq, bq, Wk, bk, Wv, bv);
    k_zsum<<<dim3(TT / 128, NP), 128>>>();
    k_out<<<dim3(TT / 128, NP), 128>>>();
    k_fc_mma<<<(NN * TT) / 128, 256>>>(Wfc, bfc, out);
}

// round 16
// speedup vs baseline: 1.0962x; 1.0477x over previous
#include <cuda_runtime.h>
#include <cuda_fp16.h>
#include <cstdint>

// Problem constants: B=1, N=16, T=2048, E=64, H=4, D=16
#define NN   16
#define TT   2048
#define EE   64
#define HH   4
#define DD   16
#define NP   (NN*HH)          // 64 (n,h) pairs
// Q pre-scaled by log2(e)/8 so scores are in log2 domain -> ex2.approx (1 MUFU)
#define QSCALE2 0.180336880740290f

// ---------------------------------------------------------------------------
// Scratch (static device arrays; allocation-free per harness rules)
__device__ __align__(16) __half g_Qh[NP * TT * DD];  // q*log2e/8 (fp16)
__device__ __align__(16) __half g_Kh[NP * TT * DD];  // k (fp16)
__device__ __align__(16) float  g_V [NP * TT * DD];  // projected v (fp32)
__device__ __align__(16) __half g_Wh[NP * TT * DD];  // (v/Z) fp16
__device__ __align__(16) __half g_Oh[NN * TT * EE];  // attention out fp16

// ---------------------------------------------------------------------------
__device__ __forceinline__ uint32_t smem_u32(const void* p) {
    return (uint32_t)__cvta_generic_to_shared(p);
}
__device__ __forceinline__ void cp16(uint32_t dst, const void* src) {
    asm volatile("cp.async.cg.shared.global [%0], [%1], 16;" :: "r"(dst), "l"(src));
}
#define CP_COMMIT() asm volatile("cp.async.commit_group;")
#define CP_WAIT(n)  asm volatile("cp.async.wait_group %0;" :: "n"(n))

#define LDSM_X4(r0,r1,r2,r3,addr) \
    asm volatile("ldmatrix.sync.aligned.m8n8.x4.shared.b16 {%0,%1,%2,%3}, [%4];" \
        : "=r"(r0),"=r"(r1),"=r"(r2),"=r"(r3) : "r"(addr))
#define LDSM_X4T(r0,r1,r2,r3,addr) \
    asm volatile("ldmatrix.sync.aligned.m8n8.x4.trans.shared.b16 {%0,%1,%2,%3}, [%4];" \
        : "=r"(r0),"=r"(r1),"=r"(r2),"=r"(r3) : "r"(addr))
#define MMA16816(c0,c1,c2,c3,a0,a1,a2,a3,b0,b1) \
    asm volatile("mma.sync.aligned.m16n8k16.row.col.f32.f16.f16.f32 " \
        "{%0,%1,%2,%3},{%4,%5,%6,%7},{%8,%9},{%0,%1,%2,%3};" \
        : "+f"(c0),"+f"(c1),"+f"(c2),"+f"(c3) \
        : "r"(a0),"r"(a1),"r"(a2),"r"(a3),"r"(b0),"r"(b1))

__device__ __forceinline__ uint32_t h2u(__half2 h) {
    return reinterpret_cast<uint32_t&>(h);
}
__device__ __forceinline__ __half2 u2h(uint32_t u) {
    return reinterpret_cast<__half2&>(u);
}
// packed fp16x2 exp2 (1 MUFU op for 2 exps)
__device__ __forceinline__ uint32_t EX2H2(float a, float b) {
    uint32_t hin = h2u(__float22half2_rn(make_float2(a, b)));
    uint32_t r;
    asm("ex2.approx.f16x2 %0, %1;" : "=r"(r) : "r"(hin));
    return r;
}

// ---------------------------------------------------------------------------
// K1: head projections -> fp16 Q (log2e-scaled), fp16 K, fp32 V.
__global__ void k_proj(const float* __restrict__ value,
                       const float* __restrict__ key,
                       const float* __restrict__ query,
                       const float* __restrict__ Wq, const float* __restrict__ bq,
                       const float* __restrict__ Wk, const float* __restrict__ bk,
                       const float* __restrict__ Wv, const float* __restrict__ bv)
{
    __shared__ float sWq[256], sWk[256], sWv[256];
    __shared__ float sbq[16], sbk[16], sbv[16];
    int tid = threadIdx.x;
    if (tid < 256) { sWq[tid] = Wq[tid]; sWk[tid] = Wk[tid]; sWv[tid] = Wv[tid]; }
    if (tid < 16)  { sbq[tid] = bq[tid]; sbk[tid] = bk[tid]; sbv[tid] = bv[tid]; }
    __syncthreads();

    int id = blockIdx.x * blockDim.x + tid;
    int t  = id & (TT - 1);
    int p  = id >> 11;
    int n  = p >> 2;
    int h  = p & 3;
    int in_base  = (n * TT + t) * EE + h * DD;
    int out_base = (p * TT + t) * DD;

    float x[16];
    // ---- q (scaled by log2e/8) ----
    #pragma unroll
    for (int i = 0; i < 16; i++) x[i] = query[in_base + i];
    {
        float a[16];
        #pragma unroll
        for (int j = 0; j < 16; j++) {
            float acc = sbq[j];
            #pragma unroll
            for (int i = 0; i < 16; i++) acc = fmaf(x[i], sWq[i * 16 + j], acc);
            a[j] = acc * QSCALE2;
        }
        __half2* dh = reinterpret_cast<__half2*>(&g_Qh[out_base]);
        #pragma unroll
        for (int j = 0; j < 8; j++)
            dh[j] = __float22half2_rn(make_float2(a[2 * j], a[2 * j + 1]));
    }
    // ---- k ----
    #pragma unroll
    for (int i = 0; i < 16; i++) x[i] = key[in_base + i];
    {
        float a[16];
        #pragma unroll
        for (int j = 0; j < 16; j++) {
            float acc = sbk[j];
            #pragma unroll
            for (int i = 0; i < 16; i++) acc = fmaf(x[i], sWk[i * 16 + j], acc);
            a[j] = acc;
        }
        __half2* dh = reinterpret_cast<__half2*>(&g_Kh[out_base]);
        #pragma unroll
        for (int j = 0; j < 8; j++)
            dh[j] = __float22half2_rn(make_float2(a[2 * j], a[2 * j + 1]));
    }
    // ---- v (fp32) ----
    #pragma unroll
    for (int i = 0; i < 16; i++) x[i] = value[in_base + i];
    #pragma unroll
    for (int j = 0; j < 16; j++) {
        float acc = sbv[j];
        #pragma unroll
        for (int i = 0; i < 16; i++) acc = fmaf(x[i], sWv[i * 16 + j], acc);
        g_V[out_base + j] = acc;
    }
}

// ---------------------------------------------------------------------------
// K2 (pass A): Z[k] = sum_q exp2(qh.kh), then fold 1/Z into V in-place.
// S hi-only; exp via ex2.approx.f16x2 (bit-consistent with k_out's P path).
// Exps accumulated in packed fp16 (HADD2) over 4-sub windows (8 terms per
// half-slot, overflow-safe), flushed to f32 -> post-exp scalar ops cut ~2.7x.
// Z window noise ~2.5e-4 (32 windows of 8, fp16 eps random-walk).
// grid = (TT/128, NP), block = 128.
__global__ void __launch_bounds__(128) k_zsum()
{
    __shared__ __align__(16) __half sK[128 * 16];
    __shared__ __align__(16) __half sQ[3][128 * 16];
    __shared__ float sZ[128];

    int tid = threadIdx.x, lane = tid & 31, warp = tid >> 5;
    int p = blockIdx.y, kbase = blockIdx.x * 128;

    // stage this block's 128 K rows: 256 uint4, 2 per thread
    {
        const uint4* src = reinterpret_cast<const uint4*>(g_Kh + (p * TT + kbase) * DD);
        uint4* dst = reinterpret_cast<uint4*>(sK);
        dst[tid * 2] = src[tid * 2];
        dst[tid * 2 + 1] = src[tid * 2 + 1];
    }

    const __half* gq = g_Qh + p * TT * DD;
    // prologue: stage Q tiles 0, 1 (256 uint4 each, 2 per thread)
    #pragma unroll
    for (int qt0 = 0; qt0 < 2; qt0++) {
        uint32_t d = smem_u32(&sQ[qt0][0]);
        cp16(d + (tid * 2) * 16,     gq + qt0 * 128 * DD + (tid * 2) * 8);
        cp16(d + (tid * 2 + 1) * 16, gq + qt0 * 128 * DD + (tid * 2 + 1) * 8);
        CP_COMMIT();
    }

    __syncthreads();   // K tile visible

    // A frags: 2 sets of 16 K rows
    int g = lane >> 3;
    uint32_t akh[2][4];
    #pragma unroll
    for (int s = 0; s < 2; s++) {
        int row = warp * 32 + s * 16 + (g & 1) * 8 + (lane & 7);
        int col = (g >> 1) * 8;
        LDSM_X4(akh[s][0], akh[s][1], akh[s][2], akh[s][3], smem_u32(&sK[row * 16 + col]));
    }

    float z[2][2] = {{0.f, 0.f}, {0.f, 0.f}};
    __half2 zh[2][2];
    #pragma unroll
    for (int s = 0; s < 2; s++)
        #pragma unroll
        for (int j = 0; j < 2; j++) zh[s][j] = __halves2half2(__ushort_as_half(0), __ushort_as_half(0));
    int browq = (g >> 1) * 8 + (lane & 7);
    int bcol  = (g & 1) * 8;

    for (int qt = 0; qt < 16; qt++) {
        if (qt < 15) { CP_WAIT(1); } else { CP_WAIT(0); }
        __syncthreads();
        int buf = qt % 3;
        uint32_t qb = smem_u32(&sQ[buf][browq * 16 + bcol]);
        #pragma unroll
        for (int sub = 0; sub < 8; sub++) {
            uint32_t bh0, bh1, bh2, bh3;
            LDSM_X4(bh0, bh1, bh2, bh3, qb + sub * 512);
            #pragma unroll
            for (int s = 0; s < 2; s++) {
                #pragma unroll
                for (int nh = 0; nh < 2; nh++) {
                    float c0 = 0.f, c1 = 0.f, c2 = 0.f, c3 = 0.f;
                    if (nh == 0) {
                        MMA16816(c0, c1, c2, c3, akh[s][0], akh[s][1], akh[s][2], akh[s][3], bh0, bh1);
                    } else {
                        MMA16816(c0, c1, c2, c3, akh[s][0], akh[s][1], akh[s][2], akh[s][3], bh2, bh3);
                    }
                    zh[s][0] = __hadd2(zh[s][0], u2h(EX2H2(c0, c1)));
                    zh[s][1] = __hadd2(zh[s][1], u2h(EX2H2(c2, c3)));
                }
            }
            // flush packed windows to f32 every 4 subs (8 terms per half-slot)
            if ((sub & 3) == 3) {
                #pragma unroll
                for (int s = 0; s < 2; s++)
                    #pragma unroll
                    for (int j = 0; j < 2; j++) {
                        float2 f = __half22float2(zh[s][j]);
                        z[s][j] += f.x + f.y;
                        zh[s][j] = __halves2half2(__ushort_as_half(0), __ushort_as_half(0));
                    }
            }
        }
        // stage tile qt+2
        if (qt + 2 < 16) {
            uint32_t d = smem_u32(&sQ[(qt + 2) % 3][0]);
            cp16(d + (tid * 2) * 16,     gq + (qt + 2) * 128 * DD + (tid * 2) * 8);
            cp16(d + (tid * 2 + 1) * 16, gq + (qt + 2) * 128 * DD + (tid * 2 + 1) * 8);
            CP_COMMIT();
        }
    }

    // quad reduce across the 4 threads sharing each row -> sZ
    #pragma unroll
    for (int s = 0; s < 2; s++)
        #pragma unroll
        for (int j = 0; j < 2; j++) {
            z[s][j] += __shfl_xor_sync(0xffffffffu, z[s][j], 1);
            z[s][j] += __shfl_xor_sync(0xffffffffu, z[s][j], 2);
        }
    if ((lane & 3) == 0) {
        int r = lane >> 2;
        #pragma unroll
        for (int s = 0; s < 2; s++) {
            sZ[warp * 32 + s * 16 + r]     = z[s][0];
            sZ[warp * 32 + s * 16 + r + 8] = z[s][1];
        }
    }
    __syncthreads();

    // fused fold: thread owns one k row; W[k,:] = V[k,:]/Z[k] (fp16)
    {
        int id = p * TT + kbase + tid;
        float inv = 1.0f / sZ[tid];
        const float4* v4 = reinterpret_cast<const float4*>(&g_V[id * DD]);
        __half2* dh = reinterpret_cast<__half2*>(&g_Wh[id * DD]);
        #pragma unroll
        for (int i = 0; i < 4; i++) {
            float4 x = v4[i];
            dh[2 * i]     = __float22half2_rn(make_float2(x.x * inv, x.y * inv));
            dh[2 * i + 1] = __float22half2_rn(make_float2(x.z * inv, x.w * inv));
        }
    }
}

// ---------------------------------------------------------------------------
// K4 (pass B): out[q,:] = sum_k exp2(qh.kh) * W[k,:]  (W pre-folded, fp16).
// S hi-only; P via ex2.approx.f16x2 (bit-consistent with k_zsum); W fp16.
// Warp owns 32 q rows.  64-k chunks, 3-deep cp.async.
// grid = (TT/128, NP), block = 128.
__global__ void __launch_bounds__(128) k_out()
{
    __shared__ __align__(16) __half sQh[128 * 16];
    __shared__ __align__(16) __half sB[3][2][64 * 16];   // [buf][Kh,Wh]

    int tid = threadIdx.x, lane = tid & 31, warp = tid >> 5;
    int p = blockIdx.y, qbase = blockIdx.x * 128;
    int n = p >> 2, h = p & 3;

    // stage this block's 128 Q rows: 256 uint4, 2 per thread
    {
        const uint4* src = reinterpret_cast<const uint4*>(g_Qh + (p * TT + qbase) * DD);
        uint4* dst = reinterpret_cast<uint4*>(sQh);
        dst[tid * 2] = src[tid * 2];
        dst[tid * 2 + 1] = src[tid * 2 + 1];
    }

    const __half* gk = g_Kh + p * TT * DD;
    const __half* gwh = g_Wh + p * TT * DD;
    uint32_t sb_base = smem_u32(&sB[0][0][0]);
    const uint32_t BUFB = 2 * 64 * 16 * 2;   // 4096 bytes per buffer

    // prologue: stage chunks 0, 1 (2 arrays x 128 slots; 2 cp16/thread)
    #pragma unroll
    for (int c0 = 0; c0 < 2; c0++) {
        uint32_t d = sb_base + c0 * BUFB;
        cp16(d + tid * 16,        gk  + c0 * 64 * DD + tid * 8);
        cp16(d + 2048 + tid * 16, gwh + c0 * 64 * DD + tid * 8);
        CP_COMMIT();
    }

    __syncthreads();   // Q tile visible

    // A frags: 2 sets of 16 Q rows
    int g = lane >> 3;
    uint32_t aqh[2][4];
    #pragma unroll
    for (int s = 0; s < 2; s++) {
        int row = warp * 32 + s * 16 + (g & 1) * 8 + (lane & 7);
        int col = (g >> 1) * 8;
        LDSM_X4(aqh[s][0], aqh[s][1], aqh[s][2], aqh[s][3], smem_u32(&sQh[row * 16 + col]));
    }

    float oc[2][2][4];   // [set][d-half][frag]
    #pragma unroll
    for (int s = 0; s < 2; s++)
        #pragma unroll
        for (int dh2 = 0; dh2 < 2; dh2++)
            #pragma unroll
            for (int j = 0; j < 4; j++) oc[s][dh2][j] = 0.f;

    uint32_t koff = ((g >> 1) * 8 + (lane & 7)) * 32 + (g & 1) * 16;
    uint32_t woff = 2048 + ((g & 1) * 8 + (lane & 7)) * 32 + (g >> 1) * 16;

    for (int kc = 0; kc < 32; kc++) {
        if (kc < 31) { CP_WAIT(1); } else { CP_WAIT(0); }
        __syncthreads();
        uint32_t bufb = sb_base + (kc % 3) * BUFB;
        uint32_t kaddr = bufb + koff;
        uint32_t waddr = bufb + woff;
        #pragma unroll
        for (int sub = 0; sub < 4; sub++) {
            uint32_t kh0, kh1, kh2, kh3;
            LDSM_X4(kh0, kh1, kh2, kh3, kaddr + sub * 512);
            uint32_t wh0, wh1, wh2, wh3;
            LDSM_X4T(wh0, wh1, wh2, wh3, waddr + sub * 512);

            #pragma unroll
            for (int s = 0; s < 2; s++) {
                uint32_t pah[4];
                {
                    float c0 = 0.f, c1 = 0.f, c2 = 0.f, c3 = 0.f;
                    MMA16816(c0, c1, c2, c3, aqh[s][0], aqh[s][1], aqh[s][2], aqh[s][3], kh0, kh1);
                    pah[0] = EX2H2(c0, c1);
                    pah[1] = EX2H2(c2, c3);
                }
                {
                    float c0 = 0.f, c1 = 0.f, c2 = 0.f, c3 = 0.f;
                    MMA16816(c0, c1, c2, c3, aqh[s][0], aqh[s][1], aqh[s][2], aqh[s][3], kh2, kh3);
                    pah[2] = EX2H2(c0, c1);
                    pah[3] = EX2H2(c2, c3);
                }

                MMA16816(oc[s][0][0], oc[s][0][1], oc[s][0][2], oc[s][0][3],
                         pah[0], pah[1], pah[2], pah[3], wh0, wh1);
                MMA16816(oc[s][1][0], oc[s][1][1], oc[s][1][2], oc[s][1][3],
                         pah[0], pah[1], pah[2], pah[3], wh2, wh3);
            }
        }
        // stage chunk kc+2
        if (kc + 2 < 32) {
            uint32_t d = sb_base + ((kc + 2) % 3) * BUFB;
            cp16(d + tid * 16,        gk  + (kc + 2) * 64 * DD + tid * 8);
            cp16(d + 2048 + tid * 16, gwh + (kc + 2) * 64 * DD + tid * 8);
            CP_COMMIT();
        }
    }

    // epilogue: write fp16 fragments to g_Oh (both sets)
    {
        int r = lane >> 2, c2 = lane & 3;
        #pragma unroll
        for (int s = 0; s < 2; s++) {
            int q0 = qbase + warp * 32 + s * 16 + r;
            int b0i = (n * TT + q0) * EE + h * DD;
            int b8i = (n * TT + q0 + 8) * EE + h * DD;
            *reinterpret_cast<__half2*>(&g_Oh[b0i + 2 * c2]) =
                __float22half2_rn(make_float2(oc[s][0][0], oc[s][0][1]));
            *reinterpret_cast<__half2*>(&g_Oh[b8i + 2 * c2]) =
                __float22half2_rn(make_float2(oc[s][0][2], oc[s][0][3]));
            *reinterpret_cast<__half2*>(&g_Oh[b0i + 8 + 2 * c2]) =
                __float22half2_rn(make_float2(oc[s][1][0], oc[s][1][1]));
            *reinterpret_cast<__half2*>(&g_Oh[b8i + 8 + 2 * c2]) =
                __float22half2_rn(make_float2(oc[s][1][2], oc[s][1][3]));
        }
    }
}

// ---------------------------------------------------------------------------
// K5: final FC via HMMA: y = O @ Wfc + bfc.  X fp16 via cp.async (fired
// first, overlaps the Wfc float4 loads — kernel was latency-bound on 16
// serial scalar Wfc LDGs).  Wfc split hi/lo in-kernel.
// grid = 256 blocks x 128 rows; block = 256 (8 warps, warp owns 16 rows).
__global__ void __launch_bounds__(256) k_fc_mma(const float* __restrict__ Wfc,
                                               const float* __restrict__ bfc,
                                               float* __restrict__ out)
{
    __shared__ __align__(16) __half sXh[128 * 64];
    __shared__ __align__(16) __half sWh[64 * 64],  sWl[64 * 64];
    __shared__ float sb[64];

    int tid = threadIdx.x, lane = tid & 31, warp = tid >> 5;
    int rowbase = blockIdx.x * 128;

    // X via cp.async (in flight while we chew Wfc)
    {
        const __half* gx = g_Oh + rowbase * EE;
        uint32_t d = smem_u32(sXh);
        #pragma unroll
        for (int j = 0; j < 4; j++) {
            int o = tid + j * 256;               // uint4 slot (1024 total)
            cp16(d + o * 16, gx + o * 8);
        }
        CP_COMMIT();
    }
    // Wfc: 1024 float4, 4 per thread; split hi/lo into smem
    #pragma unroll
    for (int j = 0; j < 4; j++) {
        int i4 = tid + j * 256;
        float4 w = reinterpret_cast<const float4*>(Wfc)[i4];
        int i = i4 * 4;
        __half h0 = __float2half_rn(w.x), h1 = __float2half_rn(w.y);
        __half h2 = __float2half_rn(w.z), h3 = __float2half_rn(w.w);
        *reinterpret_cast<__half2*>(&sWh[i])     = __halves2half2(h0, h1);
        *reinterpret_cast<__half2*>(&sWh[i + 2]) = __halves2half2(h2, h3);
        *reinterpret_cast<__half2*>(&sWl[i]) = __halves2half2(
            __float2half_rn(w.x - __half2float(h0)), __float2half_rn(w.y - __half2float(h1)));
        *reinterpret_cast<__half2*>(&sWl[i + 2]) = __halves2half2(
            __float2half_rn(w.z - __half2float(h2)), __float2half_rn(w.w - __half2float(h3)));
    }
    if (tid < 64) sb[tid] = bfc[tid];
    CP_WAIT(0);
    __syncthreads();

    int g = lane >> 3;
    uint32_t axh[4][4];
    #pragma unroll
    for (int kt = 0; kt < 4; kt++) {
        int row = warp * 16 + (g & 1) * 8 + (lane & 7);
        int col = kt * 16 + (g >> 1) * 8;
        LDSM_X4(axh[kt][0], axh[kt][1], axh[kt][2], axh[kt][3], smem_u32(&sXh[row * 64 + col]));
    }

    float c[8][4];
    #pragma unroll
    for (int i = 0; i < 8; i++)
        #pragma unroll
        for (int j = 0; j < 4; j++) c[i][j] = 0.f;

    #pragma unroll
    for (int nt2 = 0; nt2 < 4; nt2++) {
        #pragma unroll
        for (int kt = 0; kt < 4; kt++) {
            int brow = kt * 16 + (g & 1) * 8 + (lane & 7);
            int bcol = nt2 * 16 + (g >> 1) * 8;
            uint32_t bh0, bh1, bh2, bh3, bl0, bl1, bl2, bl3;
            LDSM_X4T(bh0, bh1, bh2, bh3, smem_u32(&sWh[brow * 64 + bcol]));
            LDSM_X4T(bl0, bl1, bl2, bl3, smem_u32(&sWl[brow * 64 + bcol]));
            MMA16816(c[nt2*2][0], c[nt2*2][1], c[nt2*2][2], c[nt2*2][3],
                     axh[kt][0], axh[kt][1], axh[kt][2], axh[kt][3], bh0, bh1);
            MMA16816(c[nt2*2][0], c[nt2*2][1], c[nt2*2][2], c[nt2*2][3],
                     axh[kt][0], axh[kt][1], axh[kt][2], axh[kt][3], bl0, bl1);
            MMA16816(c[nt2*2+1][0], c[nt2*2+1][1], c[nt2*2+1][2], c[nt2*2+1][3],
                     axh[kt][0], axh[kt][1], axh[kt][2], axh[kt][3], bh2, bh3);
            MMA16816(c[nt2*2+1][0], c[nt2*2+1][1], c[nt2*2+1][2], c[nt2*2+1][3],
                     axh[kt][0], axh[kt][1], axh[kt][2], axh[kt][3], bl2, bl3);
        }
    }

    int r = lane >> 2, j = lane & 3;
    int row0 = rowbase + warp * 16 + r;
    #pragma unroll
    for (int nt = 0; nt < 8; nt++) {
        int ncol = nt * 8 + 2 * j;
        float b0 = sb[ncol], b1 = sb[ncol + 1];
        *reinterpret_cast<float2*>(&out[row0 * 64 + ncol]) =
            make_float2(c[nt][0] + b0, c[nt][1] + b1);
        *reinterpret_cast<float2*>(&out[(row0 + 8) * 64 + ncol]) =
            make_float2(c[nt][2] + b0, c[nt][3] + b1);
    }
}

// ---------------------------------------------------------------------------
// Input order: 0:value 1:key 2:query 3:Wq 4:bq 5:Wk 6:bk 7:Wv 8:bv 9:Wfc 10:bfc
extern "C" void kernel_launch(void* const* d_in, const int* in_sizes, int n_in,
                              void* d_out, int out_size)
{
    const float* value = (const float*)d_in[0];
    const float* key_  = (const float*)d_in[1];
    const float* query = (const float*)d_in[2];
    const float* Wq    = (const float*)d_in[3];
    const float* bq    = (const float*)d_in[4];
    const float* Wk    = (const float*)d_in[5];
    const float* bk    = (const float*)d_in[6];
    const float* Wv    = (const float*)d_in[7];
    const float* bv    = (const float*)d_in[8];
    const float* Wfc   = (const float*)d_in[9];
    const float* bfc   = (const float*)d_in[10];
    float* out = (float*)d_out;

    k_proj<<<(NP * TT) / 256, 256>>>(value, key_, query, Wq, bq, Wk, bk, Wv, bv);
    k_zsum<<<dim3(TT / 128, NP), 128>>>();
    k_out<<<dim3(TT / 128, NP), 128>>>();
    k_fc_mma<<<(NN * TT) / 128, 256>>>(Wfc, bfc, out);
}